// round 9
// baseline (speedup 1.0000x reference)
#include <cuda_runtime.h>
#include <cstddef>

// ---------------------------------------------------------------------------
// DRTScorer: out[b,p] = sum_k alpha[b,k] * <qhat[b,k,:], dhat[p,k,:]>
// B=64, P=100000, E=384, H=512, K=6, SUB=64  (all fp32)
//
// Pipeline:
//   1) query_kernel: Qw[b, k*64+u] = alpha[b,k] * qhat[b,k,u]      (64 x 384)
//   2) H = relu(doc @ W1 + b1)                                      (P x 512)
//   3) S = H @ W2 + b2                                              (P x 384)
//   4) per-row per-64-chunk L2 normalize of S (in place)
//   5) out = Qw @ S^T                                               (64 x P)
// ---------------------------------------------------------------------------

#define MAX_P 100000
#define MAX_B 64

// scratch (device globals -- allocation-free per harness rules)
__device__ __align__(16) static float g_H [(size_t)MAX_P * 512];
__device__ __align__(16) static float g_S [(size_t)MAX_P * 384];
__device__ __align__(16) static float g_Qw[(size_t)MAX_B * 384];

// ---------------------------------------------------------------------------
// Kernel 1: per-query encode + alphas, folded into Qw.  One block per query.
// ---------------------------------------------------------------------------
__global__ __launch_bounds__(512)
void query_kernel(const float* __restrict__ q_emb,
                  const float* __restrict__ W1,  const float* __restrict__ b1,
                  const float* __restrict__ W2,  const float* __restrict__ b2,
                  const float* __restrict__ Wa1, const float* __restrict__ ba1,
                  const float* __restrict__ Wa2, const float* __restrict__ ba2,
                  float* __restrict__ Qw)
{
    __shared__ float q[384];
    __shared__ float h[512];
    __shared__ float s[384];
    __shared__ float ha[64];
    __shared__ float lg[6];
    __shared__ float alpha[6];
    __shared__ float csum[6];

    const int b = blockIdx.x;
    const int t = threadIdx.x;

    if (t < 384) q[t] = q_emb[(size_t)b * 384 + t];
    __syncthreads();

    // h = relu(q @ W1 + b1)   -- 512 outputs, one per thread
    {
        float acc = b1[t];
        #pragma unroll 8
        for (int e = 0; e < 384; e++) acc = fmaf(q[e], W1[(size_t)e * 512 + t], acc);
        h[t] = fmaxf(acc, 0.0f);
    }
    __syncthreads();

    // s = h @ W2 + b2 (threads 0..383); ha = relu(q @ Wa1 + ba1) (threads 384..447)
    if (t < 384) {
        float acc = b2[t];
        #pragma unroll 8
        for (int e = 0; e < 512; e++) acc = fmaf(h[e], W2[(size_t)e * 384 + t], acc);
        s[t] = acc;
    } else if (t < 448) {
        const int j = t - 384;
        float acc = ba1[j];
        #pragma unroll 8
        for (int e = 0; e < 384; e++) acc = fmaf(q[e], Wa1[(size_t)e * 64 + j], acc);
        ha[j] = fmaxf(acc, 0.0f);
    }
    __syncthreads();

    // logits + per-chunk sum of squares (threads 0..5)
    if (t < 6) {
        float acc = ba2[t];
        #pragma unroll 8
        for (int e = 0; e < 64; e++) acc = fmaf(ha[e], Wa2[(size_t)e * 6 + t], acc);
        lg[t] = acc;

        float ss = 0.0f;
        #pragma unroll 8
        for (int j = 0; j < 64; j++) { float v = s[t * 64 + j]; ss = fmaf(v, v, ss); }
        csum[t] = ss;
    }
    __syncthreads();

    if (t == 0) {
        float m = lg[0];
        #pragma unroll
        for (int i = 1; i < 6; i++) m = fmaxf(m, lg[i]);
        float e[6], sum = 0.0f;
        #pragma unroll
        for (int i = 0; i < 6; i++) { e[i] = expf(lg[i] - m); sum += e[i]; }
        #pragma unroll
        for (int i = 0; i < 6; i++) alpha[i] = e[i] / sum;
    }
    __syncthreads();

    if (t < 384) {
        const int c = t >> 6;
        const float inv = alpha[c] * rsqrtf(csum[c] + 1e-12f);
        Qw[(size_t)b * 384 + t] = s[t] * inv;
    }
}

// ---------------------------------------------------------------------------
// Kernel 2/3: SGEMM  C[M,N] = op(A[M,K] @ B[K,N] + bias[N]),  op = relu or id
// BM=128, BN=128, BK=16, 256 threads, 8x8 register tile per thread.
// K and N are exact multiples of BK/BN; only M is ragged.
// ---------------------------------------------------------------------------
template <bool RELU>
__global__ __launch_bounds__(256, 2)
void sgemm_bias(const float* __restrict__ A, const float* __restrict__ B,
                const float* __restrict__ bias, float* __restrict__ C,
                int M, int N, int K)
{
    constexpr int BM = 128, BN = 128, BK = 16;
    __shared__ float As[BK][BM + 4];   // transposed A tile (padded)
    __shared__ float Bs[BK][BN];

    const int tid = threadIdx.x;
    const int tx = tid & 15;           // 0..15 -> N
    const int ty = tid >> 4;           // 0..15 -> M
    const int rowBase = blockIdx.y * BM;
    const int colBase = blockIdx.x * BN;

    // A load: 2 x float4 per thread (128 rows x 16 cols)
    const int arow0 = tid >> 2;        // 0..63
    const int acg   = (tid & 3) * 4;   // k sub-offset
    // B load: 2 x float4 per thread (16 rows x 128 cols)
    const int brow0 = tid >> 5;        // 0..7
    const int bcol  = (tid & 31) * 4;

    float acc[8][8];
    #pragma unroll
    for (int i = 0; i < 8; i++)
        #pragma unroll
        for (int j = 0; j < 8; j++) acc[i][j] = 0.0f;

    for (int k0 = 0; k0 < K; k0 += BK) {
        #pragma unroll
        for (int i = 0; i < 2; i++) {
            const int r  = arow0 + i * 64;
            int gr = rowBase + r; if (gr >= M) gr = M - 1;  // clamp; epilogue guards
            const float4 f = *reinterpret_cast<const float4*>(&A[(size_t)gr * K + k0 + acg]);
            As[acg + 0][r] = f.x; As[acg + 1][r] = f.y;
            As[acg + 2][r] = f.z; As[acg + 3][r] = f.w;
        }
        #pragma unroll
        for (int i = 0; i < 2; i++) {
            const int r = brow0 + i * 8;
            const float4 f = *reinterpret_cast<const float4*>(&B[(size_t)(k0 + r) * N + colBase + bcol]);
            *reinterpret_cast<float4*>(&Bs[r][bcol]) = f;
        }
        __syncthreads();

        #pragma unroll
        for (int k = 0; k < BK; k++) {
            const float4 a0 = *reinterpret_cast<const float4*>(&As[k][ty * 8]);
            const float4 a1 = *reinterpret_cast<const float4*>(&As[k][ty * 8 + 4]);
            const float4 c0 = *reinterpret_cast<const float4*>(&Bs[k][tx * 8]);
            const float4 c1 = *reinterpret_cast<const float4*>(&Bs[k][tx * 8 + 4]);
            const float a[8]  = {a0.x, a0.y, a0.z, a0.w, a1.x, a1.y, a1.z, a1.w};
            const float bb[8] = {c0.x, c0.y, c0.z, c0.w, c1.x, c1.y, c1.z, c1.w};
            #pragma unroll
            for (int i = 0; i < 8; i++)
                #pragma unroll
                for (int j = 0; j < 8; j++)
                    acc[i][j] = fmaf(a[i], bb[j], acc[i][j]);
        }
        __syncthreads();
    }

    // epilogue: bias (+relu), guarded on M
    #pragma unroll
    for (int i = 0; i < 8; i++) {
        const int gr = rowBase + ty * 8 + i;
        if (gr >= M) break;
        #pragma unroll
        for (int j = 0; j < 8; j += 4) {
            const int gc = colBase + tx * 8 + j;
            float4 v;
            v.x = acc[i][j + 0] + bias[gc + 0];
            v.y = acc[i][j + 1] + bias[gc + 1];
            v.z = acc[i][j + 2] + bias[gc + 2];
            v.w = acc[i][j + 3] + bias[gc + 3];
            if (RELU) {
                v.x = fmaxf(v.x, 0.0f); v.y = fmaxf(v.y, 0.0f);
                v.z = fmaxf(v.z, 0.0f); v.w = fmaxf(v.w, 0.0f);
            }
            *reinterpret_cast<float4*>(&C[(size_t)gr * N + gc]) = v;
        }
    }
}

// ---------------------------------------------------------------------------
// Kernel 4: per-row per-64-chunk L2 normalize (in place). One row per block,
// one warp per chunk (2 elems per lane). Fully coalesced.
// ---------------------------------------------------------------------------
__global__ __launch_bounds__(192)
void normalize_kernel(float* __restrict__ S)
{
    const int row  = blockIdx.x;
    const int w    = threadIdx.x >> 5;
    const int lane = threadIdx.x & 31;
    float* p = S + (size_t)row * 384 + w * 64;
    const float v0 = p[lane];
    const float v1 = p[lane + 32];
    float ss = fmaf(v0, v0, v1 * v1);
    #pragma unroll
    for (int o = 16; o > 0; o >>= 1) ss += __shfl_xor_sync(0xffffffffu, ss, o);
    const float inv = rsqrtf(ss + 1e-12f);
    p[lane]      = v0 * inv;
    p[lane + 32] = v1 * inv;
}

// ---------------------------------------------------------------------------
// Kernel 5: out[64, P] = Qw[64, 384] @ S^T.  Tile 64 x 256, BK=16, 256 thr,
// 8(b) x 8(p) register tile per thread.
// ---------------------------------------------------------------------------
__global__ __launch_bounds__(256, 2)
void score_kernel(const float* __restrict__ Qw, const float* __restrict__ S,
                  float* __restrict__ out, int P)
{
    constexpr int BN = 256, BK = 16;
    __shared__ float Qs[BK][64 + 4];
    __shared__ float Ss[BK][BN + 4];

    const int tid = threadIdx.x;
    const int tx = tid & 31;   // 0..31 -> p
    const int ty = tid >> 5;   // 0..7  -> b
    const int pBase = blockIdx.x * BN;

    const int qr  = tid >> 2;          // 0..63
    const int qcg = (tid & 3) * 4;

    float acc[8][8];
    #pragma unroll
    for (int i = 0; i < 8; i++)
        #pragma unroll
        for (int j = 0; j < 8; j++) acc[i][j] = 0.0f;

    for (int k0 = 0; k0 < 384; k0 += BK) {
        {
            const float4 f = *reinterpret_cast<const float4*>(&Qw[(size_t)qr * 384 + k0 + qcg]);
            Qs[qcg + 0][qr] = f.x; Qs[qcg + 1][qr] = f.y;
            Qs[qcg + 2][qr] = f.z; Qs[qcg + 3][qr] = f.w;
        }
        #pragma unroll
        for (int i = 0; i < 4; i++) {
            const int idx = tid + i * 256;
            const int p   = idx >> 2;          // 0..255
            const int cg  = (idx & 3) * 4;
            int gp = pBase + p; if (gp >= P) gp = P - 1;
            const float4 f = *reinterpret_cast<const float4*>(&S[(size_t)gp * 384 + k0 + cg]);
            Ss[cg + 0][p] = f.x; Ss[cg + 1][p] = f.y;
            Ss[cg + 2][p] = f.z; Ss[cg + 3][p] = f.w;
        }
        __syncthreads();

        #pragma unroll
        for (int k = 0; k < BK; k++) {
            const float4 a0 = *reinterpret_cast<const float4*>(&Qs[k][ty * 8]);
            const float4 a1 = *reinterpret_cast<const float4*>(&Qs[k][ty * 8 + 4]);
            const float4 c0 = *reinterpret_cast<const float4*>(&Ss[k][tx * 8]);
            const float4 c1 = *reinterpret_cast<const float4*>(&Ss[k][tx * 8 + 4]);
            const float a[8]  = {a0.x, a0.y, a0.z, a0.w, a1.x, a1.y, a1.z, a1.w};
            const float bb[8] = {c0.x, c0.y, c0.z, c0.w, c1.x, c1.y, c1.z, c1.w};
            #pragma unroll
            for (int i = 0; i < 8; i++)
                #pragma unroll
                for (int j = 0; j < 8; j++)
                    acc[i][j] = fmaf(a[i], bb[j], acc[i][j]);
        }
        __syncthreads();
    }

    #pragma unroll
    for (int i = 0; i < 8; i++) {
        const int b = ty * 8 + i;
        #pragma unroll
        for (int j = 0; j < 8; j++) {
            const int gp = pBase + tx * 8 + j;
            if (gp < P) out[(size_t)b * P + gp] = acc[i][j];
        }
    }
}

// ---------------------------------------------------------------------------
// launch
// ---------------------------------------------------------------------------
extern "C" void kernel_launch(void* const* d_in, const int* in_sizes, int n_in,
                              void* d_out, int out_size)
{
    const float* q_emb = (const float*)d_in[0];
    const float* doc   = (const float*)d_in[1];
    const float* W1    = (const float*)d_in[2];
    const float* b1    = (const float*)d_in[3];
    const float* W2    = (const float*)d_in[4];
    const float* b2    = (const float*)d_in[5];
    const float* Wa1   = (const float*)d_in[6];
    const float* ba1   = (const float*)d_in[7];
    const float* Wa2   = (const float*)d_in[8];
    const float* ba2   = (const float*)d_in[9];
    float* out = (float*)d_out;

    const int B = in_sizes[0] / 384;   // 64
    const int P = in_sizes[1] / 384;   // 100000

    float *dH, *dS, *dQw;
    cudaGetSymbolAddress((void**)&dH,  g_H);
    cudaGetSymbolAddress((void**)&dS,  g_S);
    cudaGetSymbolAddress((void**)&dQw, g_Qw);

    // 1) queries -> Qw
    query_kernel<<<B, 512>>>(q_emb, W1, b1, W2, b2, Wa1, ba1, Wa2, ba2, dQw);

    // 2) H = relu(doc @ W1 + b1)    (P x 512, K = 384)
    {
        dim3 grid(512 / 128, (P + 127) / 128);
        sgemm_bias<true><<<grid, 256>>>(doc, W1, b1, dH, P, 512, 384);
    }

    // 3) S = H @ W2 + b2            (P x 384, K = 512)
    {
        dim3 grid(384 / 128, (P + 127) / 128);
        sgemm_bias<false><<<grid, 256>>>(dH, W2, b2, dS, P, 384, 512);
    }

    // 4) per-chunk L2 normalize (in place)
    normalize_kernel<<<P, 192>>>(dS);

    // 5) out = Qw @ S^T
    score_kernel<<<(P + 255) / 256, 256>>>(dQw, dS, out, P);
}